// round 2
// baseline (speedup 1.0000x reference)
#include <cuda_runtime.h>
#include <math.h>

#define Bv   4
#define Cv   64
#define Hv   160
#define Wv   160
#define HWv  (Hv*Wv)
#define KKv  9
#define OMC  27
#define OMCP 28          // padded
#define CKK  576

// dcn config
#define TPB   320        // threads
#define PHC   8          // channels per phase
#define PHR   72         // rows per phase = PHC*9
#define NPH   8
#define WROW  164        // window cols (x-2 .. x+161)
#define WINR  6          // window rows (y-2 .. y+3)
#define NTAB  (KKv*Wv)   // 1440 table entries

// scratch
__device__ float g_om[Bv*OMC*HWv];
__device__ float g_mid[Bv*Cv*HWv];
__device__ float g_wt1[CKK*Cv];   // transposed weights [ck][o]
__device__ float g_wt2[CKK*Cv];

typedef unsigned long long ull;

__device__ __forceinline__ ull pack2(float a, float b) {
    ull r;
    asm("mov.b64 %0, {%1,%2};" : "=l"(r) : "r"(__float_as_uint(a)), "r"(__float_as_uint(b)));
    return r;
}
__device__ __forceinline__ void ffma2(ull& d, ull a, ull b) {
    asm("fma.rn.f32x2 %0, %1, %2, %0;" : "+l"(d) : "l"(a), "l"(b));
}
__device__ __forceinline__ float lo32(ull v) { return __uint_as_float((unsigned)v); }
__device__ __forceinline__ float hi32(ull v) { return __uint_as_float((unsigned)(v >> 32)); }

__device__ __forceinline__ float gelu_exact(float v) {
    return 0.5f * v * (1.0f + erff(v * 0.70710678118654752f));
}

// ---------------------------------------------------------------------------
__global__ void transpose_w_kernel(const float* __restrict__ w1,
                                   const float* __restrict__ w2)
{
    int i = blockIdx.x * 256 + threadIdx.x;
    if (i < CKK * Cv) {
        int o = i / CKK, ck = i % CKK;
        g_wt1[ck*Cv + o] = w1[i];
        g_wt2[ck*Cv + o] = w2[i];
    }
}

// ---------------------------------------------------------------------------
// offset/mask conv with packed f32x2 over output-channel pairs.
// 256 threads, 512 px/block, each thread 2 px, 14 f32x2 acc per px.
// ---------------------------------------------------------------------------
__global__ __launch_bounds__(256) void offset_conv_kernel(
    const float* __restrict__ src,
    const float* __restrict__ w,     // [27][64][3][3]
    const float* __restrict__ bias,
    float* __restrict__ om)
{
    extern __shared__ float sw[];          // [576][28] + bias[28]
    float* sb = sw + CKK*OMCP;
    for (int i = threadIdx.x; i < OMC*CKK; i += 256) {
        int o = i / CKK, ck = i % CKK;     // coalesced gmem read
        sw[ck*OMCP + o] = w[i];
    }
    for (int i = threadIdx.x; i < CKK; i += 256) sw[i*OMCP + 27] = 0.f;
    if (threadIdx.x < OMCP) sb[threadIdx.x] = (threadIdx.x < OMC) ? bias[threadIdx.x] : 0.f;
    __syncthreads();

    int base = blockIdx.x * 512;
    int p0 = base + threadIdx.x;
    int p1 = p0 + 256;
    int b0 = p0 / HWv, r0 = p0 % HWv, y0 = r0 / Wv, x0 = r0 % Wv;
    int b1 = p1 / HWv, r1 = p1 % HWv, y1 = r1 / Wv, x1 = r1 % Wv;

    ull acc0[14], acc1[14];
    #pragma unroll
    for (int j = 0; j < 14; j++) { acc0[j] = 0ULL; acc1[j] = 0ULL; }

    const float* s0 = src + (size_t)b0 * Cv * HWv;
    const float* s1 = src + (size_t)b1 * Cv * HWv;

    for (int c = 0; c < Cv; c++) {
        const float* xc0 = s0 + c*HWv;
        const float* xc1 = s1 + c*HWv;
        #pragma unroll
        for (int ky = 0; ky < 3; ky++) {
            int yy0 = y0 + ky - 1, yy1 = y1 + ky - 1;
            bool vy0 = (unsigned)yy0 < (unsigned)Hv;
            bool vy1 = (unsigned)yy1 < (unsigned)Hv;
            #pragma unroll
            for (int kx = 0; kx < 3; kx++) {
                int xx0 = x0 + kx - 1, xx1 = x1 + kx - 1;
                float v0 = (vy0 && (unsigned)xx0 < (unsigned)Wv) ? __ldg(xc0 + yy0*Wv + xx0) : 0.f;
                float v1 = (vy1 && (unsigned)xx1 < (unsigned)Wv) ? __ldg(xc1 + yy1*Wv + xx1) : 0.f;
                ull v00 = pack2(v0, v0);
                ull v11 = pack2(v1, v1);
                const float* wp = &sw[(c*9 + ky*3 + kx)*OMCP];
                #pragma unroll
                for (int j = 0; j < 14; j++) {
                    ull w2 = *(const ull*)&wp[2*j];   // LDS.64 broadcast
                    ffma2(acc0[j], v00, w2);
                    ffma2(acc1[j], v11, w2);
                }
            }
        }
    }
    float a0[OMCP], a1[OMCP];
    #pragma unroll
    for (int j = 0; j < 14; j++) {
        a0[2*j] = lo32(acc0[j]); a0[2*j+1] = hi32(acc0[j]);
        a1[2*j] = lo32(acc1[j]); a1[2*j+1] = hi32(acc1[j]);
    }
    #pragma unroll
    for (int o = 0; o < OMC; o++) {
        om[((size_t)b0*OMC + o)*HWv + y0*Wv + x0] = a0[o] + sb[o];
        om[((size_t)b1*OMC + o)*HWv + y1*Wv + x1] = a1[o] + sb[o];
    }
}

// ---------------------------------------------------------------------------
// Fused DCN + BN (+residual) + GELU. One block = one full row (160 px) of one
// (b, y). 8 phases of 8 channels: stage input window in SMEM, sample, GEMM.
// GEMM: 16 og x 20 pxg threads, each 4o x 8px with f32x2 accumulators.
// ---------------------------------------------------------------------------
__global__ __launch_bounds__(TPB, 2) void dcn_kernel(
    const float* __restrict__ src,
    const float* __restrict__ wt,    // transposed [576][64]
    const float* __restrict__ bng,
    const float* __restrict__ bnb,
    const float* __restrict__ bnm,
    const float* __restrict__ bnv,
    const float* __restrict__ identity,
    float* __restrict__ out)
{
    extern __shared__ char smemraw[];
    float*  sSamp = (float*)smemraw;                              // [72][160]
    float4* sWgt4 = (float4*)(smemraw + PHR*Wv*4);                // [1440]
    float*  sWin  = (float*)(smemraw + PHR*Wv*4 + NTAB*16);       // [8][6][164]
    int*    sWbase= (int*)  (smemraw + PHR*Wv*4 + NTAB*16 + PHC*WINR*WROW*4);
    unsigned* sFall = (unsigned*)((char*)sWbase + NTAB*4);

    const int y = blockIdx.x;
    const int b = blockIdx.y;
    const int tid = threadIdx.x;

    // --- Phase A: per-(k,px) gather tables ---
    const float* omB = g_om + (size_t)b*OMC*HWv + y*Wv;
    for (int idx = tid; idx < NTAB; idx += TPB) {
        int k = idx / Wv, px = idx - k*Wv;
        float dy = omB[(2*k  )*HWv + px];
        float dx = omB[(2*k+1)*HWv + px];
        float mr = omB[(18+k )*HWv + px];
        float m  = 1.f / (1.f + expf(-mr));
        float py  = (float)y  - 1.f + (float)(k/3) + dy;
        float pxf = (float)px - 1.f + (float)(k%3) + dx;
        float yf = floorf(py), xf = floorf(pxf);
        float ly = py - yf, lx = pxf - xf;
        int iy0 = (int)yf, ix0 = (int)xf;
        float vy0 = ((unsigned)iy0     < (unsigned)Hv) ? 1.f : 0.f;
        float vy1 = ((unsigned)(iy0+1) < (unsigned)Hv) ? 1.f : 0.f;
        float vx0 = ((unsigned)ix0     < (unsigned)Wv) ? 1.f : 0.f;
        float vx1 = ((unsigned)(ix0+1) < (unsigned)Wv) ? 1.f : 0.f;
        sWgt4[idx] = make_float4((1.f-ly)*(1.f-lx)*m*vy0*vx0,
                                 (1.f-ly)*lx      *m*vy0*vx1,
                                 ly      *(1.f-lx)*m*vy1*vx0,
                                 ly      *lx      *m*vy1*vx1);
        int r0 = iy0 - (y-2);
        int c0 = ix0 + 2;
        bool inw = ((unsigned)r0 <= 4u) && ((unsigned)c0 <= (unsigned)(WROW-2));
        sWbase[idx] = inw ? (r0*WROW + c0) : -1;
        int iy0c = min(max(iy0,0),Hv-1), iy1c = min(max(iy0+1,0),Hv-1);
        int ix0c = min(max(ix0,0),Wv-1), ix1c = min(max(ix0+1,0),Wv-1);
        sFall[idx] = (unsigned)iy0c | ((unsigned)iy1c<<8) | ((unsigned)ix0c<<16) | ((unsigned)ix1c<<24);
    }

    ull acc[4][4];
    #pragma unroll
    for (int i = 0; i < 4; i++)
        #pragma unroll
        for (int j = 0; j < 4; j++) acc[i][j] = 0ULL;

    const int og  = tid & 15;     // 16 groups of 4 output channels
    const int pxg = tid >> 4;     // 20 groups of 8 px
    const float* srcB = src + (size_t)b*Cv*HWv;
    const int px0 = (tid < Wv) ? tid : tid - Wv;   // sampling px (tid%160)
    const int tb  = (tid < Wv) ? 0 : 1;            // tid/160

    __syncthreads();   // tables ready

    for (int ph = 0; ph < NPH; ph++) {
        // --- stage window: 8 ch x 6 rows x 164 cols ---
        for (int i = tid; i < PHC*WINR*WROW; i += TPB) {
            int cl  = i / (WINR*WROW);
            int rem = i - cl*(WINR*WROW);
            int r   = rem / WROW;
            int cc  = rem - r*WROW;
            int gy = y - 2 + r, gx = cc - 2;
            float v = 0.f;
            if ((unsigned)gy < (unsigned)Hv && (unsigned)gx < (unsigned)Wv)
                v = __ldg(srcB + (size_t)(ph*PHC+cl)*HWv + gy*Wv + gx);
            sWin[i] = v;
        }
        __syncthreads();  // window ready; prev GEMM done with sSamp

        // --- sample 72 rows x 160 px ---
        #pragma unroll 4
        for (int i2 = 0; i2 < (PHR*Wv)/TPB; i2++) {
            int row = i2*2 + tb;              // 0..71
            int cl = row / 9, k = row - 9*cl;
            int g = k*Wv + px0;
            int wb = sWbase[g];
            float4 cw = sWgt4[g];
            const float* winc = sWin + cl*(WINR*WROW);
            float s;
            if (wb >= 0) {
                s = cw.x*winc[wb] + cw.y*winc[wb+1]
                  + cw.z*winc[wb+WROW] + cw.w*winc[wb+WROW+1];
            } else {
                unsigned f = sFall[g];
                int iy0 = f & 255, iy1 = (f>>8)&255, ix0 = (f>>16)&255, ix1 = f>>24;
                const float* xc = srcB + (size_t)(ph*PHC+cl)*HWv;
                s = cw.x*__ldg(xc+iy0*Wv+ix0) + cw.y*__ldg(xc+iy0*Wv+ix1)
                  + cw.z*__ldg(xc+iy1*Wv+ix0) + cw.w*__ldg(xc+iy1*Wv+ix1);
            }
            sSamp[row*Wv + px0] = s;
        }
        __syncthreads();  // samples ready

        // --- GEMM over this phase's 72 ck rows ---
        const float* wph = wt + (size_t)ph*PHR*Cv;
        #pragma unroll 2
        for (int cki = 0; cki < PHR; cki++) {
            float4 wv = __ldg((const float4*)(wph + cki*Cv + og*4));
            const ull* sp = (const ull*)(sSamp + cki*Wv + pxg*8);
            ull s0 = sp[0], s1 = sp[1], s2 = sp[2], s3 = sp[3];
            ull w0 = pack2(wv.x, wv.x);
            ull w1 = pack2(wv.y, wv.y);
            ull w2 = pack2(wv.z, wv.z);
            ull w3 = pack2(wv.w, wv.w);
            ffma2(acc[0][0], w0, s0); ffma2(acc[0][1], w0, s1);
            ffma2(acc[0][2], w0, s2); ffma2(acc[0][3], w0, s3);
            ffma2(acc[1][0], w1, s0); ffma2(acc[1][1], w1, s1);
            ffma2(acc[1][2], w1, s2); ffma2(acc[1][3], w1, s3);
            ffma2(acc[2][0], w2, s0); ffma2(acc[2][1], w2, s1);
            ffma2(acc[2][2], w2, s2); ffma2(acc[2][3], w2, s3);
            ffma2(acc[3][0], w3, s0); ffma2(acc[3][1], w3, s1);
            ffma2(acc[3][2], w3, s2); ffma2(acc[3][3], w3, s3);
        }
        // no sync here: next staging touches sWin (samples already consumed
        // before the pre-GEMM sync? No — staging(ph+1) overwrites sWin which
        // sampling(ph) read; sampling finished before the pre-GEMM sync, and
        // sSamp reuse is guarded by the post-staging sync above.)
    }

    // --- epilogue: BN (+residual) + exact GELU ---
    const int xg = pxg*8;
    #pragma unroll
    for (int op = 0; op < 4; op++) {
        int o = og*4 + op;
        float sc = bng[o] * rsqrtf(bnv[o] + 1e-5f);
        float sh = bnb[o] - bnm[o]*sc;
        float r[8];
        #pragma unroll
        for (int pp = 0; pp < 4; pp++) {
            r[2*pp]   = lo32(acc[op][pp]) * sc + sh;
            r[2*pp+1] = hi32(acc[op][pp]) * sc + sh;
        }
        size_t off = (size_t)b*Cv*HWv + (size_t)o*HWv + y*Wv + xg;
        if (identity) {
            float4 i0 = __ldg((const float4*)(identity + off));
            float4 i1 = __ldg((const float4*)(identity + off + 4));
            r[0]+=i0.x; r[1]+=i0.y; r[2]+=i0.z; r[3]+=i0.w;
            r[4]+=i1.x; r[5]+=i1.y; r[6]+=i1.z; r[7]+=i1.w;
        }
        #pragma unroll
        for (int i = 0; i < 8; i++) r[i] = gelu_exact(r[i]);
        *(float4*)(out + off)     = make_float4(r[0],r[1],r[2],r[3]);
        *(float4*)(out + off + 4) = make_float4(r[4],r[5],r[6],r[7]);
    }
}

// ---------------------------------------------------------------------------
extern "C" void kernel_launch(void* const* d_in, const int* in_sizes, int n_in,
                              void* d_out, int out_size)
{
    const float* x      = (const float*)d_in[0];
    const float* w_om1  = (const float*)d_in[1];
    const float* b_om1  = (const float*)d_in[2];
    const float* w_dcn1 = (const float*)d_in[3];
    const float* bn1g   = (const float*)d_in[4];
    const float* bn1b   = (const float*)d_in[5];
    const float* bn1m   = (const float*)d_in[6];
    const float* bn1v   = (const float*)d_in[7];
    const float* w_om2  = (const float*)d_in[8];
    const float* b_om2  = (const float*)d_in[9];
    const float* w_dcn2 = (const float*)d_in[10];
    const float* bn2g   = (const float*)d_in[11];
    const float* bn2b   = (const float*)d_in[12];
    const float* bn2m   = (const float*)d_in[13];
    const float* bn2v   = (const float*)d_in[14];
    float* out = (float*)d_out;

    float *om = nullptr, *mid = nullptr, *wt1 = nullptr, *wt2 = nullptr;
    cudaGetSymbolAddress((void**)&om,  g_om);
    cudaGetSymbolAddress((void**)&mid, g_mid);
    cudaGetSymbolAddress((void**)&wt1, g_wt1);
    cudaGetSymbolAddress((void**)&wt2, g_wt2);

    const int smem_off = (CKK*OMCP + OMCP) * sizeof(float);
    const int smem_dcn = PHR*Wv*4 + NTAB*16 + PHC*WINR*WROW*4 + NTAB*4 + NTAB*4;
    cudaFuncSetAttribute(offset_conv_kernel, cudaFuncAttributeMaxDynamicSharedMemorySize, smem_off);
    cudaFuncSetAttribute(dcn_kernel,         cudaFuncAttributeMaxDynamicSharedMemorySize, smem_dcn);

    transpose_w_kernel<<<(CKK*Cv + 255)/256, 256>>>(w_dcn1, w_dcn2);

    dim3 dcn_grid(Hv, Bv);

    offset_conv_kernel<<<(Bv*HWv)/512, 256, smem_off>>>(x, w_om1, b_om1, om);
    dcn_kernel<<<dcn_grid, TPB, smem_dcn>>>(x, wt1, bn1g, bn1b, bn1m, bn1v, nullptr, mid);

    offset_conv_kernel<<<(Bv*HWv)/512, 256, smem_off>>>(mid, w_om2, b_om2, om);
    dcn_kernel<<<dcn_grid, TPB, smem_dcn>>>(mid, wt2, bn2g, bn2b, bn2m, bn2v, x, out);
}

// round 3
// speedup vs baseline: 1.1474x; 1.1474x over previous
#include <cuda_runtime.h>
#include <math.h>

#define Bv   4
#define Cv   64
#define Hv   160
#define Wv   160
#define HWv  (Hv*Wv)
#define KKv  9
#define OMC  27
#define OMCP 28
#define CKK  576

// dcn config
#define TPB   160
#define TILE  80          // pixels per dcn tile (half row)
#define PHC   4           // channels per phase
#define PHR   36          // rows per phase
#define NPH   16
#define WINC  84          // window cols
#define WINR  6
#define WINSZ (PHC*WINR*WINC)   // 2016
#define NTAB  (KKv*TILE)        // 720
#define STG_IT ((WINSZ + TPB - 1)/TPB)  // 13

// scratch
__device__ float g_om[Bv*OMC*HWv];
__device__ float g_mid[Bv*Cv*HWv];
__device__ float g_wt1[CKK*Cv];   // transposed weights [ck][o]
__device__ float g_wt2[CKK*Cv];

typedef unsigned long long ull;

__device__ __forceinline__ ull pack2(float a, float b) {
    ull r;
    asm("mov.b64 %0, {%1,%2};" : "=l"(r) : "r"(__float_as_uint(a)), "r"(__float_as_uint(b)));
    return r;
}
__device__ __forceinline__ void ffma2(ull& d, ull a, ull b) {
    asm("fma.rn.f32x2 %0, %1, %2, %0;" : "+l"(d) : "l"(a), "l"(b));
}
__device__ __forceinline__ float lo32(ull v) { return __uint_as_float((unsigned)v); }
__device__ __forceinline__ float hi32(ull v) { return __uint_as_float((unsigned)(v >> 32)); }

__device__ __forceinline__ float gelu_exact(float v) {
    return 0.5f * v * (1.0f + erff(v * 0.70710678118654752f));
}

// ---------------------------------------------------------------------------
__global__ void transpose_w_kernel(const float* __restrict__ w1,
                                   const float* __restrict__ w2)
{
    int i = blockIdx.x * 256 + threadIdx.x;
    if (i < CKK * Cv) {
        int o = i / CKK, ck = i % CKK;
        g_wt1[ck*Cv + o] = w1[i];
        g_wt2[ck*Cv + o] = w2[i];
    }
}

// ---------------------------------------------------------------------------
// offset/mask conv. Block = 256 px. Two thread-halves each own 14 of the 28
// (padded) output channels; each thread: 2 px x 14 o = 14 f32x2 accumulators.
// ---------------------------------------------------------------------------
__global__ __launch_bounds__(256, 3) void offset_conv_kernel(
    const float* __restrict__ src,
    const float* __restrict__ w,     // [27][64][3][3]
    const float* __restrict__ bias,
    float* __restrict__ om)
{
    extern __shared__ float sw[];          // [576][28] + bias[28]
    float* sb = sw + CKK*OMCP;
    for (int i = threadIdx.x; i < OMC*CKK; i += 256) {
        int o = i / CKK, ck = i % CKK;
        sw[ck*OMCP + o] = w[i];
    }
    for (int i = threadIdx.x; i < CKK; i += 256) sw[i*OMCP + 27] = 0.f;
    if (threadIdx.x < OMCP) sb[threadIdx.x] = (threadIdx.x < OMC) ? bias[threadIdx.x] : 0.f;
    __syncthreads();

    const int lane = threadIdx.x & 127;
    const int h    = threadIdx.x >> 7;       // o-half: 0 -> o 0..13, 1 -> o 14..27
    const int hofs = h * 14;

    int p0 = blockIdx.x * 256 + lane;
    int p1 = p0 + 128;
    int b0 = p0 / HWv, r0 = p0 % HWv, y0 = r0 / Wv, x0 = r0 % Wv;
    int b1 = p1 / HWv, r1 = p1 % HWv, y1 = r1 / Wv, x1 = r1 % Wv;

    ull acc0[7], acc1[7];
    #pragma unroll
    for (int j = 0; j < 7; j++) { acc0[j] = 0ULL; acc1[j] = 0ULL; }

    const float* s0 = src + (size_t)b0 * Cv * HWv;
    const float* s1 = src + (size_t)b1 * Cv * HWv;

    for (int c = 0; c < Cv; c++) {
        const float* xc0 = s0 + c*HWv;
        const float* xc1 = s1 + c*HWv;
        #pragma unroll
        for (int ky = 0; ky < 3; ky++) {
            int yy0 = y0 + ky - 1, yy1 = y1 + ky - 1;
            bool vy0 = (unsigned)yy0 < (unsigned)Hv;
            bool vy1 = (unsigned)yy1 < (unsigned)Hv;
            #pragma unroll
            for (int kx = 0; kx < 3; kx++) {
                int xx0 = x0 + kx - 1, xx1 = x1 + kx - 1;
                float v0 = (vy0 && (unsigned)xx0 < (unsigned)Wv) ? __ldg(xc0 + yy0*Wv + xx0) : 0.f;
                float v1 = (vy1 && (unsigned)xx1 < (unsigned)Wv) ? __ldg(xc1 + yy1*Wv + xx1) : 0.f;
                ull v00 = pack2(v0, v0);
                ull v11 = pack2(v1, v1);
                const ull* wp = (const ull*)&sw[(c*9 + ky*3 + kx)*OMCP + hofs];
                #pragma unroll
                for (int j = 0; j < 7; j++) {
                    ull wv = wp[j];          // LDS.64 broadcast
                    ffma2(acc0[j], v00, wv);
                    ffma2(acc1[j], v11, wv);
                }
            }
        }
    }
    #pragma unroll
    for (int j = 0; j < 7; j++) {
        #pragma unroll
        for (int e = 0; e < 2; e++) {
            int o = hofs + 2*j + e;
            if (o < OMC) {
                float a0 = (e ? hi32(acc0[j]) : lo32(acc0[j])) + sb[o];
                float a1 = (e ? hi32(acc1[j]) : lo32(acc1[j])) + sb[o];
                om[((size_t)b0*OMC + o)*HWv + y0*Wv + x0] = a0;
                om[((size_t)b1*OMC + o)*HWv + y1*Wv + x1] = a1;
            }
        }
    }
}

// ---------------------------------------------------------------------------
// Fused DCN + BN (+residual) + GELU. Block = 80-px half-row of one (b,y).
// 16 phases of 4 channels. Double-buffered input window; staging for phase
// ph+1 is register-prefetched and overlapped with the GEMM of phase ph.
// GEMM: 16 og x 10 pxg threads, each 4 o x 8 px with f32x2 accumulators.
// ---------------------------------------------------------------------------
__global__ __launch_bounds__(TPB, 5) void dcn_kernel(
    const float* __restrict__ src,
    const float* __restrict__ wt,    // transposed [576][64]
    const float* __restrict__ bng,
    const float* __restrict__ bnb,
    const float* __restrict__ bnm,
    const float* __restrict__ bnv,
    const float* __restrict__ identity,
    float* __restrict__ out)
{
    extern __shared__ char smemraw[];
    float*  sSamp  = (float*)smemraw;                    // [36][80]  11520 B
    float4* sWgt4  = (float4*)(smemraw + 11520);         // [720]     11520 B
    int*    sWbase = (int*)(smemraw + 23040);            // [720]      2880 B
    float*  sWin   = (float*)(smemraw + 25920);          // [2][2016] 16128 B

    const int x0t = blockIdx.x * TILE;
    const int y   = blockIdx.y;
    const int b   = blockIdx.z;
    const int tid = threadIdx.x;

    const float* srcB = src + (size_t)b*Cv*HWv;

    // --- Phase A: per-(k,px) gather tables ---
    const float* omB = g_om + (size_t)b*OMC*HWv + y*Wv;
    for (int idx = tid; idx < NTAB; idx += TPB) {
        int k = idx / TILE, px = idx - k*TILE;
        int xx = x0t + px;
        float dy = omB[(2*k  )*HWv + xx];
        float dx = omB[(2*k+1)*HWv + xx];
        float mr = omB[(18+k )*HWv + xx];
        float m  = 1.f / (1.f + expf(-mr));
        float py  = (float)y  - 1.f + (float)(k/3) + dy;
        float pxf = (float)xx - 1.f + (float)(k%3) + dx;
        float yf = floorf(py), xf = floorf(pxf);
        float ly = py - yf, lx = pxf - xf;
        int iy0 = (int)yf, ix0 = (int)xf;
        float vy0 = ((unsigned)iy0     < (unsigned)Hv) ? 1.f : 0.f;
        float vy1 = ((unsigned)(iy0+1) < (unsigned)Hv) ? 1.f : 0.f;
        float vx0 = ((unsigned)ix0     < (unsigned)Wv) ? 1.f : 0.f;
        float vx1 = ((unsigned)(ix0+1) < (unsigned)Wv) ? 1.f : 0.f;
        sWgt4[idx] = make_float4((1.f-ly)*(1.f-lx)*m*vy0*vx0,
                                 (1.f-ly)*lx      *m*vy0*vx1,
                                 ly      *(1.f-lx)*m*vy1*vx0,
                                 ly      *lx      *m*vy1*vx1);
        int wr = iy0 - (y - 2);
        int wc = ix0 - x0t + 2;
        if ((unsigned)wr <= 4u && (unsigned)wc <= (unsigned)(WINC - 2)) {
            sWbase[idx] = wr*WINC + wc;
        } else {
            int iy0c = min(max(iy0,0),Hv-1), ix0c = min(max(ix0,0),Wv-1);
            int enc = iy0c | (ix0c<<8) | ((iy0>=0)<<16) | ((ix0>=0)<<17);
            sWbase[idx] = -1 - enc;
        }
    }

    // --- initial window stage (phase 0 -> buf 0) ---
    for (int i = tid; i < WINSZ; i += TPB) {
        int cl  = i / (WINR*WINC);
        int rem = i - cl*(WINR*WINC);
        int r   = rem / WINC;
        int cc  = rem - r*WINC;
        int gy = y - 2 + r, gx = x0t - 2 + cc;
        float v = 0.f;
        if ((unsigned)gy < (unsigned)Hv && (unsigned)gx < (unsigned)Wv)
            v = __ldg(srcB + (size_t)cl*HWv + gy*Wv + gx);
        sWin[i] = v;
    }

    ull acc[4][4];
    #pragma unroll
    for (int i = 0; i < 4; i++)
        #pragma unroll
        for (int j = 0; j < 4; j++) acc[i][j] = 0ULL;

    const int og  = tid & 15;         // 16 groups of 4 output channels
    const int pxg = tid >> 4;         // 10 groups of 8 px
    const int spx   = (tid < TILE) ? tid : tid - TILE;  // sampling px
    const int shalf = (tid < TILE) ? 0 : 1;

    __syncthreads();   // tables + window(0) ready

    for (int ph = 0; ph < NPH; ph++) {
        const float* rbuf = sWin + (ph & 1)*WINSZ;
        // --- sample 36 rows x 80 px of this phase ---
        #pragma unroll 2
        for (int i = 0; i < PHR/2; i++) {
            int row = 2*i + shalf;                 // 0..35
            int cl = row / 9, k = row - 9*cl;
            int g = k*TILE + spx;
            int wb = sWbase[g];
            float4 cw = sWgt4[g];
            const float* winc = rbuf + cl*(WINR*WINC);
            float s;
            if (wb >= 0) {
                s = cw.x*winc[wb] + cw.y*winc[wb+1]
                  + cw.z*winc[wb+WINC] + cw.w*winc[wb+WINC+1];
            } else {
                int v = -1 - wb;
                int iy0 = v & 255, ix0 = (v>>8) & 255;
                int iy1 = min(iy0 + ((v>>16)&1), Hv-1);
                int ix1 = min(ix0 + ((v>>17)&1), Wv-1);
                const float* xc = srcB + (size_t)(ph*PHC + cl)*HWv;
                s = cw.x*__ldg(xc+iy0*Wv+ix0) + cw.y*__ldg(xc+iy0*Wv+ix1)
                  + cw.z*__ldg(xc+iy1*Wv+ix0) + cw.w*__ldg(xc+iy1*Wv+ix1);
            }
            sSamp[row*TILE + spx] = s;
        }
        __syncthreads();   // samples ready; rbuf fully consumed

        // --- prefetch next window into registers (overlaps with GEMM) ---
        float stg[STG_IT];
        const bool have = (ph + 1 < NPH);
        if (have) {
            const float* srcP = srcB + (size_t)(ph+1)*PHC*HWv;
            #pragma unroll
            for (int i = 0; i < STG_IT; i++) {
                int idx = i*TPB + tid;
                int cl  = idx / (WINR*WINC);
                int rem = idx - cl*(WINR*WINC);
                int r   = rem / WINC;
                int cc  = rem - r*WINC;
                int gy = y - 2 + r, gx = x0t - 2 + cc;
                float v = 0.f;
                if (idx < WINSZ && (unsigned)gy < (unsigned)Hv && (unsigned)gx < (unsigned)Wv)
                    v = __ldg(srcP + (size_t)cl*HWv + gy*Wv + gx);
                stg[i] = v;
            }
        }

        // --- GEMM over this phase's 36 ck rows ---
        const float* wph = wt + (size_t)ph*PHR*Cv;
        #pragma unroll 3
        for (int cki = 0; cki < PHR; cki++) {
            float4 wv = __ldg((const float4*)(wph + cki*Cv + og*4));
            const ull* sp = (const ull*)(sSamp + cki*TILE + pxg*8);
            ull s0 = sp[0], s1 = sp[1], s2 = sp[2], s3 = sp[3];
            ull w0 = pack2(wv.x, wv.x);
            ull w1 = pack2(wv.y, wv.y);
            ull w2 = pack2(wv.z, wv.z);
            ull w3 = pack2(wv.w, wv.w);
            ffma2(acc[0][0], w0, s0); ffma2(acc[0][1], w0, s1);
            ffma2(acc[0][2], w0, s2); ffma2(acc[0][3], w0, s3);
            ffma2(acc[1][0], w1, s0); ffma2(acc[1][1], w1, s1);
            ffma2(acc[1][2], w1, s2); ffma2(acc[1][3], w1, s3);
            ffma2(acc[2][0], w2, s0); ffma2(acc[2][1], w2, s1);
            ffma2(acc[2][2], w2, s2); ffma2(acc[2][3], w2, s3);
            ffma2(acc[3][0], w3, s0); ffma2(acc[3][1], w3, s1);
            ffma2(acc[3][2], w3, s2); ffma2(acc[3][3], w3, s3);
        }

        // --- commit prefetched window to the other buffer ---
        if (have) {
            float* wbuf = sWin + ((ph+1) & 1)*WINSZ;
            #pragma unroll
            for (int i = 0; i < STG_IT; i++) {
                int idx = i*TPB + tid;
                if (idx < WINSZ) wbuf[idx] = stg[i];
            }
        }
        __syncthreads();   // next window ready; sSamp free for overwrite
    }

    // --- epilogue: BN (+residual) + exact GELU ---
    const int xg = x0t + pxg*8;
    #pragma unroll
    for (int op = 0; op < 4; op++) {
        int o = og*4 + op;
        float sc = __ldg(bng+o) * rsqrtf(__ldg(bnv+o) + 1e-5f);
        float sh = __ldg(bnb+o) - __ldg(bnm+o)*sc;
        float r[8];
        #pragma unroll
        for (int pp = 0; pp < 4; pp++) {
            r[2*pp]   = lo32(acc[op][pp]) * sc + sh;
            r[2*pp+1] = hi32(acc[op][pp]) * sc + sh;
        }
        size_t off = (size_t)b*Cv*HWv + (size_t)o*HWv + y*Wv + xg;
        if (identity) {
            float4 i0 = __ldg((const float4*)(identity + off));
            float4 i1 = __ldg((const float4*)(identity + off + 4));
            r[0]+=i0.x; r[1]+=i0.y; r[2]+=i0.z; r[3]+=i0.w;
            r[4]+=i1.x; r[5]+=i1.y; r[6]+=i1.z; r[7]+=i1.w;
        }
        #pragma unroll
        for (int i = 0; i < 8; i++) r[i] = gelu_exact(r[i]);
        *(float4*)(out + off)     = make_float4(r[0],r[1],r[2],r[3]);
        *(float4*)(out + off + 4) = make_float4(r[4],r[5],r[6],r[7]);
    }
}

// ---------------------------------------------------------------------------
extern "C" void kernel_launch(void* const* d_in, const int* in_sizes, int n_in,
                              void* d_out, int out_size)
{
    const float* x      = (const float*)d_in[0];
    const float* w_om1  = (const float*)d_in[1];
    const float* b_om1  = (const float*)d_in[2];
    const float* w_dcn1 = (const float*)d_in[3];
    const float* bn1g   = (const float*)d_in[4];
    const float* bn1b   = (const float*)d_in[5];
    const float* bn1m   = (const float*)d_in[6];
    const float* bn1v   = (const float*)d_in[7];
    const float* w_om2  = (const float*)d_in[8];
    const float* b_om2  = (const float*)d_in[9];
    const float* w_dcn2 = (const float*)d_in[10];
    const float* bn2g   = (const float*)d_in[11];
    const float* bn2b   = (const float*)d_in[12];
    const float* bn2m   = (const float*)d_in[13];
    const float* bn2v   = (const float*)d_in[14];
    float* out = (float*)d_out;

    float *om = nullptr, *mid = nullptr, *wt1 = nullptr, *wt2 = nullptr;
    cudaGetSymbolAddress((void**)&om,  g_om);
    cudaGetSymbolAddress((void**)&mid, g_mid);
    cudaGetSymbolAddress((void**)&wt1, g_wt1);
    cudaGetSymbolAddress((void**)&wt2, g_wt2);

    const int smem_off = (CKK*OMCP + OMCP) * sizeof(float);          // 64624 B
    const int smem_dcn = 11520 + 11520 + 2880 + 2*WINSZ*4;           // 42048 B
    cudaFuncSetAttribute(offset_conv_kernel, cudaFuncAttributeMaxDynamicSharedMemorySize, smem_off);
    cudaFuncSetAttribute(dcn_kernel,         cudaFuncAttributeMaxDynamicSharedMemorySize, smem_dcn);

    transpose_w_kernel<<<(CKK*Cv + 255)/256, 256>>>(w_dcn1, w_dcn2);

    dim3 dcn_grid(Wv/TILE, Hv, Bv);   // 2 x 160 x 4 = 1280 blocks

    offset_conv_kernel<<<(Bv*HWv)/256, 256, smem_off>>>(x, w_om1, b_om1, om);
    dcn_kernel<<<dcn_grid, TPB, smem_dcn>>>(x, wt1, bn1g, bn1b, bn1m, bn1v, nullptr, mid);

    offset_conv_kernel<<<(Bv*HWv)/256, 256, smem_off>>>(mid, w_om2, b_om2, om);
    dcn_kernel<<<dcn_grid, TPB, smem_dcn>>>(mid, wt2, bn2g, bn2b, bn2m, bn2v, x, out);
}

// round 5
// speedup vs baseline: 1.4573x; 1.2701x over previous
#include <cuda_runtime.h>
#include <cuda_bf16.h>
#include <math.h>
#include <stdint.h>

#define Bv   4
#define Cv   64
#define Hv   160
#define Wv   160
#define HWv  (Hv*Wv)
#define KKv  9
#define OMC  27
#define OMCP 28
#define CKK  576

// dcn mma config
#define MT    128          // px per block tile (M)
#define NT    64           // output channels (N)
#define CKC   64           // ck per chunk (K chunk)
#define NCH   9
#define TPBD  256
#define AST   37           // padded row stride in 32-bit words (conflict-free)

// smem byte offsets
#define SMO_WGT    0                        // float4[1152]  18432
#define SMO_BASE   18432                    // int[1152]      4608
#define SMO_SC     23040                    // float[64]
#define SMO_SH     23296                    // float[64]
#define SMO_AH     23552                    // 128*37*4 = 18944
#define SMO_AL     42496                    // 18944
#define SMO_BH     61440                    // 64*37*4 = 9472
#define SMO_BL     70912                    // 9472
#define SMEM_DCN   80384

// scratch
__device__ float g_om[Bv*OMC*HWv];
__device__ float g_mid[Bv*Cv*HWv];
__device__ __nv_bfloat16 g_wh1[Cv*CKK], g_wl1[Cv*CKK];
__device__ __nv_bfloat16 g_wh2[Cv*CKK], g_wl2[Cv*CKK];

typedef unsigned long long ull;

__device__ __forceinline__ ull pack2(float a, float b) {
    ull r;
    asm("mov.b64 %0, {%1,%2};" : "=l"(r) : "r"(__float_as_uint(a)), "r"(__float_as_uint(b)));
    return r;
}
__device__ __forceinline__ void ffma2(ull& d, ull a, ull b) {
    asm("fma.rn.f32x2 %0, %1, %2, %0;" : "+l"(d) : "l"(a), "l"(b));
}
__device__ __forceinline__ float lo32(ull v) { return __uint_as_float((unsigned)v); }
__device__ __forceinline__ float hi32(ull v) { return __uint_as_float((unsigned)(v >> 32)); }

__device__ __forceinline__ float gelu_exact(float v) {
    return 0.5f * v * (1.0f + erff(v * 0.70710678118654752f));
}

// portable HMMA: m16n8k16 row.col f32.bf16.bf16.f32
__device__ __forceinline__ void mma_bf16(float* d,
    uint32_t a0, uint32_t a1, uint32_t a2, uint32_t a3,
    uint32_t b0, uint32_t b1)
{
    asm volatile(
        "mma.sync.aligned.m16n8k16.row.col.f32.bf16.bf16.f32 "
        "{%0,%1,%2,%3},{%4,%5,%6,%7},{%8,%9},{%0,%1,%2,%3};"
        : "+f"(d[0]), "+f"(d[1]), "+f"(d[2]), "+f"(d[3])
        : "r"(a0), "r"(a1), "r"(a2), "r"(a3), "r"(b0), "r"(b1));
}

// ---------------------------------------------------------------------------
// weight prep: bf16 hi/lo split, layout [o][ck]
// ---------------------------------------------------------------------------
__global__ void prep_w_kernel(const float* __restrict__ w1, const float* __restrict__ w2)
{
    int i = blockIdx.x * 256 + threadIdx.x;
    if (i < Cv*CKK) {
        float v1 = w1[i];
        __nv_bfloat16 h1 = __float2bfloat16(v1);
        g_wh1[i] = h1;
        g_wl1[i] = __float2bfloat16(v1 - __bfloat162float(h1));
        float v2 = w2[i];
        __nv_bfloat16 h2 = __float2bfloat16(v2);
        g_wh2[i] = h2;
        g_wl2[i] = __float2bfloat16(v2 - __bfloat162float(h2));
    }
}

// ---------------------------------------------------------------------------
// offset/mask conv (unchanged from R3)
// ---------------------------------------------------------------------------
__global__ __launch_bounds__(256, 3) void offset_conv_kernel(
    const float* __restrict__ src,
    const float* __restrict__ w,
    const float* __restrict__ bias,
    float* __restrict__ om)
{
    extern __shared__ float sw[];
    float* sb = sw + CKK*OMCP;
    for (int i = threadIdx.x; i < OMC*CKK; i += 256) {
        int o = i / CKK, ck = i % CKK;
        sw[ck*OMCP + o] = w[i];
    }
    for (int i = threadIdx.x; i < CKK; i += 256) sw[i*OMCP + 27] = 0.f;
    if (threadIdx.x < OMCP) sb[threadIdx.x] = (threadIdx.x < OMC) ? bias[threadIdx.x] : 0.f;
    __syncthreads();

    const int lane = threadIdx.x & 127;
    const int h    = threadIdx.x >> 7;
    const int hofs = h * 14;

    int p0 = blockIdx.x * 256 + lane;
    int p1 = p0 + 128;
    int b0 = p0 / HWv, r0 = p0 % HWv, y0 = r0 / Wv, x0 = r0 % Wv;
    int b1 = p1 / HWv, r1 = p1 % HWv, y1 = r1 / Wv, x1 = r1 % Wv;

    ull acc0[7], acc1[7];
    #pragma unroll
    for (int j = 0; j < 7; j++) { acc0[j] = 0ULL; acc1[j] = 0ULL; }

    const float* s0 = src + (size_t)b0 * Cv * HWv;
    const float* s1 = src + (size_t)b1 * Cv * HWv;

    for (int c = 0; c < Cv; c++) {
        const float* xc0 = s0 + c*HWv;
        const float* xc1 = s1 + c*HWv;
        #pragma unroll
        for (int ky = 0; ky < 3; ky++) {
            int yy0 = y0 + ky - 1, yy1 = y1 + ky - 1;
            bool vy0 = (unsigned)yy0 < (unsigned)Hv;
            bool vy1 = (unsigned)yy1 < (unsigned)Hv;
            #pragma unroll
            for (int kx = 0; kx < 3; kx++) {
                int xx0 = x0 + kx - 1, xx1 = x1 + kx - 1;
                float v0 = (vy0 && (unsigned)xx0 < (unsigned)Wv) ? __ldg(xc0 + yy0*Wv + xx0) : 0.f;
                float v1 = (vy1 && (unsigned)xx1 < (unsigned)Wv) ? __ldg(xc1 + yy1*Wv + xx1) : 0.f;
                ull v00 = pack2(v0, v0);
                ull v11 = pack2(v1, v1);
                const ull* wp = (const ull*)&sw[(c*9 + ky*3 + kx)*OMCP + hofs];
                #pragma unroll
                for (int j = 0; j < 7; j++) {
                    ull wv = wp[j];
                    ffma2(acc0[j], v00, wv);
                    ffma2(acc1[j], v11, wv);
                }
            }
        }
    }
    #pragma unroll
    for (int j = 0; j < 7; j++) {
        #pragma unroll
        for (int e = 0; e < 2; e++) {
            int o = hofs + 2*j + e;
            if (o < OMC) {
                float a0 = (e ? hi32(acc0[j]) : lo32(acc0[j])) + sb[o];
                float a1 = (e ? hi32(acc1[j]) : lo32(acc1[j])) + sb[o];
                om[((size_t)b0*OMC + o)*HWv + y0*Wv + x0] = a0;
                om[((size_t)b1*OMC + o)*HWv + y1*Wv + x1] = a1;
            }
        }
    }
}

// ---------------------------------------------------------------------------
// DCN via mma.sync bf16 (hi/lo 3-pass). Block = 128 px x 64 o, 8 warps.
// Each warp: 16-px stripe, 8 n-tiles of m16n8k16, K accumulated over 9 chunks.
// ---------------------------------------------------------------------------
__global__ __launch_bounds__(TPBD, 2) void dcn_mma_kernel(
    const float* __restrict__ src,
    const __nv_bfloat16* __restrict__ wh,
    const __nv_bfloat16* __restrict__ wl,
    const float* __restrict__ bng,
    const float* __restrict__ bnb,
    const float* __restrict__ bnm,
    const float* __restrict__ bnv,
    const float* __restrict__ identity,
    float* __restrict__ out)
{
    extern __shared__ char smem[];
    float4*   sWgt  = (float4*)(smem + SMO_WGT);
    int*      sBase = (int*)(smem + SMO_BASE);
    float*    sSc   = (float*)(smem + SMO_SC);
    float*    sSh   = (float*)(smem + SMO_SH);
    uint32_t* AH    = (uint32_t*)(smem + SMO_AH);
    uint32_t* AL    = (uint32_t*)(smem + SMO_AL);
    uint32_t* BH    = (uint32_t*)(smem + SMO_BH);
    uint32_t* BL    = (uint32_t*)(smem + SMO_BL);

    const int tid  = threadIdx.x;
    const int wid  = tid >> 5;
    const int lane = tid & 31;
    const int g    = lane >> 2;      // mma group id (row / n within 8)
    const int tq   = lane & 3;       // thread-in-group
    const int b    = blockIdx.y;
    const int P0   = blockIdx.x * MT;

    // BN coefficients
    if (tid < NT) {
        float sc = bng[tid] * rsqrtf(bnv[tid] + 1e-5f);
        sSc[tid] = sc;
        sSh[tid] = bnb[tid] - bnm[tid]*sc;
    }

    // gather tables: 9 k x 128 px
    const float* omB = g_om + (size_t)b*OMC*HWv;
    for (int idx = tid; idx < KKv*MT; idx += TPBD) {
        int k = idx >> 7, pl = idx & 127;
        int pxg = P0 + pl;
        int y = pxg / Wv, x = pxg - y*Wv;
        float dy = omB[(2*k  )*HWv + pxg];
        float dx = omB[(2*k+1)*HWv + pxg];
        float mr = omB[(18+k )*HWv + pxg];
        float m  = 1.f / (1.f + expf(-mr));
        float py  = (float)y - 1.f + (float)(k/3) + dy;
        float pxf = (float)x - 1.f + (float)(k%3) + dx;
        float yf = floorf(py), xf = floorf(pxf);
        float ly = py - yf, lx = pxf - xf;
        int iy0 = (int)yf, ix0 = (int)xf;
        float vy0 = ((unsigned)iy0     < (unsigned)Hv) ? 1.f : 0.f;
        float vy1 = ((unsigned)(iy0+1) < (unsigned)Hv) ? 1.f : 0.f;
        float vx0 = ((unsigned)ix0     < (unsigned)Wv) ? 1.f : 0.f;
        float vx1 = ((unsigned)(ix0+1) < (unsigned)Wv) ? 1.f : 0.f;
        sWgt[idx] = make_float4((1.f-ly)*(1.f-lx)*m*vy0*vx0,
                                (1.f-ly)*lx      *m*vy0*vx1,
                                ly      *(1.f-lx)*m*vy1*vx0,
                                ly      *lx      *m*vy1*vx1);
        int iy0c = min(max(iy0,0),Hv-1), ix0c = min(max(ix0,0),Wv-1);
        int dy1 = (iy0 >= 0 && iy0 <= Hv-2) ? 1 : 0;
        int dx1 = (ix0 >= 0 && ix0 <= Wv-2) ? 1 : 0;
        sBase[idx] = iy0c | (ix0c<<8) | (dy1<<16) | (dx1<<17);
    }
    __syncthreads();

    const float* srcB = src + (size_t)b*Cv*HWv;
    const int pl = tid & 127;          // sampling pixel lane
    const int jh = tid >> 7;           // j half

    float acc[8][4];
    #pragma unroll
    for (int nt = 0; nt < 8; nt++)
        #pragma unroll
        for (int e = 0; e < 4; e++) acc[nt][e] = 0.f;

    for (int cc = 0; cc < NCH; cc++) {
        if (cc) __syncthreads();   // previous mma done with A/B tiles

        // --- stage B chunk hi/lo: 64 o x 32 words ---
        #pragma unroll
        for (int it = 0; it < 8; it++) {
            int idx = it*TPBD + tid;
            int o = idx >> 5, jw = idx & 31;
            int gofs = o*CKK + cc*CKC + 2*jw;
            BH[o*AST + jw] = *(const uint32_t*)(wh + gofs);
            BL[o*AST + jw] = *(const uint32_t*)(wl + gofs);
        }

        // --- sample A chunk: 64 ck x 128 px (each thread: 2 ck x 1 px x 16) ---
        #pragma unroll 2
        for (int i = 0; i < 16; i++) {
            int jp = jh*16 + i;              // word index 0..31
            int ck0 = cc*CKC + 2*jp;
            int c0 = ck0 / 9,  k0 = ck0 - 9*c0;
            int ck1 = ck0 + 1;
            int c1 = ck1 / 9,  k1 = ck1 - 9*c1;

            int g0 = k0*MT + pl;
            float4 cw0 = sWgt[g0];
            int e0 = sBase[g0];
            int iy0 = e0 & 255, ix0 = (e0>>8) & 255;
            int iy1 = iy0 + ((e0>>16)&1), ix1 = ix0 + ((e0>>17)&1);
            const float* xc0 = srcB + (size_t)c0*HWv;
            float s0 = cw0.x*__ldg(xc0+iy0*Wv+ix0) + cw0.y*__ldg(xc0+iy0*Wv+ix1)
                     + cw0.z*__ldg(xc0+iy1*Wv+ix0) + cw0.w*__ldg(xc0+iy1*Wv+ix1);

            int g1 = k1*MT + pl;
            float4 cw1 = sWgt[g1];
            int e1 = sBase[g1];
            int jy0 = e1 & 255, jx0 = (e1>>8) & 255;
            int jy1 = jy0 + ((e1>>16)&1), jx1 = jx0 + ((e1>>17)&1);
            const float* xc1 = srcB + (size_t)c1*HWv;
            float s1 = cw1.x*__ldg(xc1+jy0*Wv+jx0) + cw1.y*__ldg(xc1+jy0*Wv+jx1)
                     + cw1.z*__ldg(xc1+jy1*Wv+jx0) + cw1.w*__ldg(xc1+jy1*Wv+jx1);

            __nv_bfloat16 h0 = __float2bfloat16(s0);
            __nv_bfloat16 h1 = __float2bfloat16(s1);
            __nv_bfloat16 l0 = __float2bfloat16(s0 - __bfloat162float(h0));
            __nv_bfloat16 l1 = __float2bfloat16(s1 - __bfloat162float(h1));
            AH[pl*AST + jp] = (uint32_t)__bfloat16_as_ushort(h0) | ((uint32_t)__bfloat16_as_ushort(h1) << 16);
            AL[pl*AST + jp] = (uint32_t)__bfloat16_as_ushort(l0) | ((uint32_t)__bfloat16_as_ushort(l1) << 16);
        }
        __syncthreads();

        // --- MMA: 4 k-steps x 8 n-tiles x 3 passes ---
        const int arow = wid*16 + g;
        #pragma unroll
        for (int ks = 0; ks < 4; ks++) {
            int ao = arow*AST + ks*8 + tq;
            uint32_t aH0 = AH[ao],          aH1 = AH[ao + 8*AST];
            uint32_t aH2 = AH[ao + 4],      aH3 = AH[ao + 8*AST + 4];
            uint32_t aL0 = AL[ao],          aL1 = AL[ao + 8*AST];
            uint32_t aL2 = AL[ao + 4],      aL3 = AL[ao + 8*AST + 4];
            #pragma unroll
            for (int nt = 0; nt < 8; nt++) {
                int bo = (nt*8 + g)*AST + ks*8 + tq;
                uint32_t bH0 = BH[bo], bH1 = BH[bo + 4];
                uint32_t bL0 = BL[bo], bL1 = BL[bo + 4];
                mma_bf16(acc[nt], aH0, aH1, aH2, aH3, bH0, bH1);
                mma_bf16(acc[nt], aH0, aH1, aH2, aH3, bL0, bL1);
                mma_bf16(acc[nt], aL0, aL1, aL2, aL3, bH0, bH1);
            }
        }
    }

    // --- epilogue: BN (+residual) + exact GELU ---
    // thread holds D[row arow + {0,8}][col nt*8 + 2tq + {0,1}]
    const int px0 = P0 + wid*16 + g;
    const size_t bofs = (size_t)b*Cv*HWv;
    #pragma unroll
    for (int nt = 0; nt < 8; nt++) {
        #pragma unroll
        for (int e = 0; e < 4; e++) {
            int o  = nt*8 + 2*tq + (e & 1);
            int px = px0 + (e >> 1)*8;
            float v = acc[nt][e] * sSc[o] + sSh[o];
            size_t ofs = bofs + (size_t)o*HWv + px;
            if (identity) v += __ldg(identity + ofs);
            out[ofs] = gelu_exact(v);
        }
    }
}

// ---------------------------------------------------------------------------
extern "C" void kernel_launch(void* const* d_in, const int* in_sizes, int n_in,
                              void* d_out, int out_size)
{
    const float* x      = (const float*)d_in[0];
    const float* w_om1  = (const float*)d_in[1];
    const float* b_om1  = (const float*)d_in[2];
    const float* w_dcn1 = (const float*)d_in[3];
    const float* bn1g   = (const float*)d_in[4];
    const float* bn1b   = (const float*)d_in[5];
    const float* bn1m   = (const float*)d_in[6];
    const float* bn1v   = (const float*)d_in[7];
    const float* w_om2  = (const float*)d_in[8];
    const float* b_om2  = (const float*)d_in[9];
    const float* w_dcn2 = (const float*)d_in[10];
    const float* bn2g   = (const float*)d_in[11];
    const float* bn2b   = (const float*)d_in[12];
    const float* bn2m   = (const float*)d_in[13];
    const float* bn2v   = (const float*)d_in[14];
    float* out = (float*)d_out;

    float *om = nullptr, *mid = nullptr;
    __nv_bfloat16 *wh1, *wl1, *wh2, *wl2;
    cudaGetSymbolAddress((void**)&om,  g_om);
    cudaGetSymbolAddress((void**)&mid, g_mid);
    cudaGetSymbolAddress((void**)&wh1, g_wh1);
    cudaGetSymbolAddress((void**)&wl1, g_wl1);
    cudaGetSymbolAddress((void**)&wh2, g_wh2);
    cudaGetSymbolAddress((void**)&wl2, g_wl2);

    const int smem_off = (CKK*OMCP + OMCP) * sizeof(float);
    cudaFuncSetAttribute(offset_conv_kernel, cudaFuncAttributeMaxDynamicSharedMemorySize, smem_off);
    cudaFuncSetAttribute(dcn_mma_kernel,     cudaFuncAttributeMaxDynamicSharedMemorySize, SMEM_DCN);

    prep_w_kernel<<<(Cv*CKK + 255)/256, 256>>>(w_dcn1, w_dcn2);

    dim3 dcn_grid(HWv/MT, Bv);   // 200 x 4

    offset_conv_kernel<<<(Bv*HWv)/256, 256, smem_off>>>(x, w_om1, b_om1, om);
    dcn_mma_kernel<<<dcn_grid, TPBD, SMEM_DCN>>>(x, wh1, wl1,
        bn1g, bn1b, bn1m, bn1v, nullptr, mid);

    offset_conv_kernel<<<(Bv*HWv)/256, 256, smem_off>>>(mid, w_om2, b_om2, om);
    dcn_mma_kernel<<<dcn_grid, TPBD, SMEM_DCN>>>(mid, wh2, wl2,
        bn2g, bn2b, bn2m, bn2v, x, out);
}

// round 6
// speedup vs baseline: 1.8656x; 1.2802x over previous
#include <cuda_runtime.h>
#include <cuda_bf16.h>
#include <math.h>
#include <stdint.h>

#define Bv   4
#define Cv   64
#define Hv   160
#define Wv   160
#define HWv  25600
#define KKv  9
#define OMC  27
#define CKK  576

#define MT    128          // px per block tile (M)
#define CKC   64           // K chunk
#define NCH   9
#define AST   36           // words/row: 144B, 16B aligned, ldmatrix conflict-free

// dcn smem offsets (bytes)
#define DS_WGT  0          // float4[1152] 18432
#define DS_BASE 18432      // int[1152]     4608
#define DS_SC   23040      // float[64]
#define DS_SH   23296      // float[64]
#define DS_AH   23552      // 128*36*4 = 18432
#define DS_AL   41984
#define DS_BH   60416      // 64*36*4 = 9216
#define DS_BL   69632
#define DS_TOT  78848

// offc smem offsets
#define OS_AH   0          // 18432
#define OS_AL   18432
#define OS_BH   36864      // 32*36*4 = 4608
#define OS_BL   41472
#define OS_BIAS 46080
#define OS_TOT  46208

// scratch
__device__ float    g_om[Bv*OMC*HWv];
__device__ float    g_mid[Bv*Cv*HWv];
__device__ uint32_t g_xhl[Bv*Cv*HWv];     // packed (bf16 hi | bf16 lo<<16)
__device__ uint32_t g_midhl[Bv*Cv*HWv];
__device__ __nv_bfloat16 g_wh1[Cv*CKK], g_wl1[Cv*CKK];
__device__ __nv_bfloat16 g_wh2[Cv*CKK], g_wl2[Cv*CKK];
__device__ __nv_bfloat16 g_omh1[32*CKK], g_oml1[32*CKK];
__device__ __nv_bfloat16 g_omh2[32*CKK], g_oml2[32*CKK];

__device__ __forceinline__ float gelu_exact(float v) {
    return 0.5f * v * (1.0f + erff(v * 0.70710678118654752f));
}
__device__ __forceinline__ uint32_t split_pack(float v) {
    __nv_bfloat16 h = __float2bfloat16(v);
    __nv_bfloat16 l = __float2bfloat16(v - __bfloat162float(h));
    return (uint32_t)__bfloat16_as_ushort(h) | ((uint32_t)__bfloat16_as_ushort(l) << 16);
}
__device__ __forceinline__ uint32_t smem_u32(const void* p) {
    uint32_t a;
    asm("{ .reg .u64 t; cvta.to.shared.u64 t, %1; cvt.u32.u64 %0, t; }" : "=r"(a) : "l"(p));
    return a;
}
__device__ __forceinline__ void mma_bf16(float* d,
    uint32_t a0, uint32_t a1, uint32_t a2, uint32_t a3, uint32_t b0, uint32_t b1)
{
    asm volatile(
        "mma.sync.aligned.m16n8k16.row.col.f32.bf16.bf16.f32 "
        "{%0,%1,%2,%3},{%4,%5,%6,%7},{%8,%9},{%0,%1,%2,%3};"
        : "+f"(d[0]), "+f"(d[1]), "+f"(d[2]), "+f"(d[3])
        : "r"(a0), "r"(a1), "r"(a2), "r"(a3), "r"(b0), "r"(b1));
}
__device__ __forceinline__ void ldm_x4(uint32_t& r0, uint32_t& r1, uint32_t& r2, uint32_t& r3, uint32_t addr) {
    asm volatile("ldmatrix.sync.aligned.m8n8.x4.shared.b16 {%0,%1,%2,%3}, [%4];"
                 : "=r"(r0), "=r"(r1), "=r"(r2), "=r"(r3) : "r"(addr));
}

// ---------------------------------------------------------------------------
// prep: split x, dcn weights, offset-conv weights (padded to 32 rows) to bf16 hi/lo
// ---------------------------------------------------------------------------
__global__ void prep_kernel(const float* __restrict__ x,
                            const float* __restrict__ wd1, const float* __restrict__ wd2,
                            const float* __restrict__ wom1, const float* __restrict__ wom2)
{
    int i = blockIdx.x * 256 + threadIdx.x;
    if (i < Bv*Cv*HWv) g_xhl[i] = split_pack(x[i]);
    if (i < Cv*CKK) {
        float v1 = wd1[i];
        __nv_bfloat16 h1 = __float2bfloat16(v1);
        g_wh1[i] = h1;
        g_wl1[i] = __float2bfloat16(v1 - __bfloat162float(h1));
        float v2 = wd2[i];
        __nv_bfloat16 h2 = __float2bfloat16(v2);
        g_wh2[i] = h2;
        g_wl2[i] = __float2bfloat16(v2 - __bfloat162float(h2));
    }
    if (i < 32*CKK) {
        float v1 = (i < OMC*CKK) ? wom1[i] : 0.f;
        __nv_bfloat16 h1 = __float2bfloat16(v1);
        g_omh1[i] = h1;
        g_oml1[i] = __float2bfloat16(v1 - __bfloat162float(h1));
        float v2 = (i < OMC*CKK) ? wom2[i] : 0.f;
        __nv_bfloat16 h2 = __float2bfloat16(v2);
        g_omh2[i] = h2;
        g_oml2[i] = __float2bfloat16(v2 - __bfloat162float(h2));
    }
}

// ---------------------------------------------------------------------------
// offset/mask conv as mma.sync implicit GEMM. M=128 px, N=32 (27 used), K=576.
// ---------------------------------------------------------------------------
__global__ __launch_bounds__(256, 4) void offc_mma_kernel(
    const uint32_t* __restrict__ xhl,
    const __nv_bfloat16* __restrict__ bwh,
    const __nv_bfloat16* __restrict__ bwl,
    const float* __restrict__ bias,
    float* __restrict__ om)
{
    extern __shared__ char smem[];
    const uint32_t sbu = smem_u32(smem);
    float* sbias = (float*)(smem + OS_BIAS);

    const int tid = threadIdx.x, wid = tid >> 5, lane = tid & 31;
    const int g = lane >> 2, tq = lane & 3;
    const int b = blockIdx.y;
    const int P0 = blockIdx.x * MT;

    if (tid < 32) sbias[tid] = (tid < OMC) ? bias[tid] : 0.f;

    const int pl = tid & 127, jh = tid >> 7;
    const int pg = P0 + pl;
    const int py = pg / Wv, px = pg - py*Wv;
    const uint32_t* src = xhl + (size_t)b*Cv*HWv;

    // ldmatrix addresses (chunk-invariant)
    const int rowA = wid*16 + (lane & 7) + ((lane & 8) ? 8 : 0);
    const int kwA  = (lane & 16) ? 4 : 0;
    const uint32_t adrAH = sbu + OS_AH + rowA*(AST*4) + kwA*4;
    const uint32_t adrAL = adrAH + (OS_AL - OS_AH);
    const int rowBl = (lane & 7) + ((lane & 16) ? 8 : 0);
    const int kwB   = (lane & 8) ? 4 : 0;
    const uint32_t adrBH0 = sbu + OS_BH + rowBl*(AST*4) + kwB*4;
    const uint32_t adrBH1 = adrBH0 + 16*(AST*4);
    const uint32_t adrBL0 = adrBH0 + (OS_BL - OS_BH);
    const uint32_t adrBL1 = adrBH1 + (OS_BL - OS_BH);

    float acc[4][4];
    #pragma unroll
    for (int nt = 0; nt < 4; nt++)
        #pragma unroll
        for (int e = 0; e < 4; e++) acc[nt][e] = 0.f;

    for (int cc = 0; cc < NCH; cc++) {
        if (cc) __syncthreads();
        // stage B: 32 o x 32 words (hi/lo)
        #pragma unroll
        for (int it = 0; it < 4; it++) {
            int idx = it*256 + tid;
            int o = idx >> 5, jw = idx & 31;
            int gofs = o*CKK + cc*CKC + 2*jw;
            *(uint32_t*)(smem + OS_BH + (o*AST + jw)*4) = *(const uint32_t*)(bwh + gofs);
            *(uint32_t*)(smem + OS_BL + (o*AST + jw)*4) = *(const uint32_t*)(bwl + gofs);
        }
        // build A: regular im2col, 16 words/thread as 4 STS.128 quads
        #pragma unroll
        for (int q = 0; q < 4; q++) {
            int jq = jh*4 + q;
            uint32_t hq[4], lq[4];
            #pragma unroll
            for (int wi = 0; wi < 4; wi++) {
                int ck0 = cc*CKC + 8*jq + 2*wi;
                uint32_t v0 = 0, v1 = 0;
                int c0 = ck0/9, k0 = ck0 - 9*c0;
                int yy0 = py + k0/3 - 1, xx0 = px + (k0 - (k0/3)*3) - 1;
                if ((unsigned)yy0 < (unsigned)Hv && (unsigned)xx0 < (unsigned)Wv)
                    v0 = __ldg(src + (size_t)c0*HWv + yy0*Wv + xx0);
                int ck1 = ck0 + 1;
                int c1 = ck1/9, k1 = ck1 - 9*c1;
                int yy1 = py + k1/3 - 1, xx1 = px + (k1 - (k1/3)*3) - 1;
                if ((unsigned)yy1 < (unsigned)Hv && (unsigned)xx1 < (unsigned)Wv)
                    v1 = __ldg(src + (size_t)c1*HWv + yy1*Wv + xx1);
                hq[wi] = __byte_perm(v0, v1, 0x5410);
                lq[wi] = __byte_perm(v0, v1, 0x7632);
            }
            *(uint4*)(smem + OS_AH + pl*(AST*4) + jq*16) = make_uint4(hq[0],hq[1],hq[2],hq[3]);
            *(uint4*)(smem + OS_AL + pl*(AST*4) + jq*16) = make_uint4(lq[0],lq[1],lq[2],lq[3]);
        }
        __syncthreads();
        // mma: 3 passes
        #pragma unroll
        for (int ks = 0; ks < 4; ks++) {
            uint32_t aH0,aH1,aH2,aH3, aL0,aL1,aL2,aL3;
            ldm_x4(aH0,aH1,aH2,aH3, adrAH + ks*32);
            ldm_x4(aL0,aL1,aL2,aL3, adrAL + ks*32);
            uint32_t bh0,bh1,bh2,bh3, bl0,bl1,bl2,bl3;
            ldm_x4(bh0,bh1,bh2,bh3, adrBH0 + ks*32);
            ldm_x4(bl0,bl1,bl2,bl3, adrBL0 + ks*32);
            mma_bf16(acc[0], aH0,aH1,aH2,aH3, bh0,bh1);
            mma_bf16(acc[0], aH0,aH1,aH2,aH3, bl0,bl1);
            mma_bf16(acc[0], aL0,aL1,aL2,aL3, bh0,bh1);
            mma_bf16(acc[1], aH0,aH1,aH2,aH3, bh2,bh3);
            mma_bf16(acc[1], aH0,aH1,aH2,aH3, bl2,bl3);
            mma_bf16(acc[1], aL0,aL1,aL2,aL3, bh2,bh3);
            ldm_x4(bh0,bh1,bh2,bh3, adrBH1 + ks*32);
            ldm_x4(bl0,bl1,bl2,bl3, adrBL1 + ks*32);
            mma_bf16(acc[2], aH0,aH1,aH2,aH3, bh0,bh1);
            mma_bf16(acc[2], aH0,aH1,aH2,aH3, bl0,bl1);
            mma_bf16(acc[2], aL0,aL1,aL2,aL3, bh0,bh1);
            mma_bf16(acc[3], aH0,aH1,aH2,aH3, bh2,bh3);
            mma_bf16(acc[3], aH0,aH1,aH2,aH3, bl2,bl3);
            mma_bf16(acc[3], aL0,aL1,aL2,aL3, bh2,bh3);
        }
    }

    // epilogue: +bias -> g_om
    #pragma unroll
    for (int nt = 0; nt < 4; nt++) {
        #pragma unroll
        for (int e = 0; e < 4; e++) {
            int o = nt*8 + 2*tq + (e & 1);
            if (o < OMC) {
                int p = P0 + wid*16 + g + (e >> 1)*8;
                om[((size_t)b*OMC + o)*HWv + p] = acc[nt][e] + sbias[o];
            }
        }
    }
}

// ---------------------------------------------------------------------------
// DCN via mma.sync bf16 3-pass + ldmatrix fragments.
// ---------------------------------------------------------------------------
__global__ __launch_bounds__(256, 2) void dcn_mma_kernel(
    const float* __restrict__ src,
    const __nv_bfloat16* __restrict__ wh,
    const __nv_bfloat16* __restrict__ wl,
    const float* __restrict__ bng,
    const float* __restrict__ bnb,
    const float* __restrict__ bnm,
    const float* __restrict__ bnv,
    const float* __restrict__ identity,
    float* __restrict__ out,
    uint32_t* __restrict__ midhl)
{
    extern __shared__ char smem[];
    const uint32_t sbu = smem_u32(smem);
    float4* sWgt  = (float4*)(smem + DS_WGT);
    int*    sBase = (int*)(smem + DS_BASE);
    float*  sSc   = (float*)(smem + DS_SC);
    float*  sSh   = (float*)(smem + DS_SH);

    const int tid  = threadIdx.x, wid = tid >> 5, lane = tid & 31;
    const int g    = lane >> 2, tq = lane & 3;
    const int b    = blockIdx.y;
    const int P0   = blockIdx.x * MT;

    if (tid < 64) {
        float sc = bng[tid] * rsqrtf(bnv[tid] + 1e-5f);
        sSc[tid] = sc;
        sSh[tid] = bnb[tid] - bnm[tid]*sc;
    }

    // gather tables: 9 k x 128 px
    const float* omB = g_om + (size_t)b*OMC*HWv;
    for (int idx = tid; idx < KKv*MT; idx += 256) {
        int k = idx >> 7, pl = idx & 127;
        int pxg = P0 + pl;
        int y = pxg / Wv, x = pxg - y*Wv;
        float dy = omB[(2*k  )*HWv + pxg];
        float dx = omB[(2*k+1)*HWv + pxg];
        float mr = omB[(18+k )*HWv + pxg];
        float m  = 1.f / (1.f + expf(-mr));
        float pyf = (float)y - 1.f + (float)(k/3) + dy;
        float pxf = (float)x - 1.f + (float)(k%3) + dx;
        float yf = floorf(pyf), xf = floorf(pxf);
        float ly = pyf - yf, lx = pxf - xf;
        int iy0 = (int)yf, ix0 = (int)xf;
        float vy0 = ((unsigned)iy0     < (unsigned)Hv) ? 1.f : 0.f;
        float vy1 = ((unsigned)(iy0+1) < (unsigned)Hv) ? 1.f : 0.f;
        float vx0 = ((unsigned)ix0     < (unsigned)Wv) ? 1.f : 0.f;
        float vx1 = ((unsigned)(ix0+1) < (unsigned)Wv) ? 1.f : 0.f;
        sWgt[idx] = make_float4((1.f-ly)*(1.f-lx)*m*vy0*vx0,
                                (1.f-ly)*lx      *m*vy0*vx1,
                                ly      *(1.f-lx)*m*vy1*vx0,
                                ly      *lx      *m*vy1*vx1);
        int iy0c = min(max(iy0,0),Hv-1), ix0c = min(max(ix0,0),Wv-1);
        int dy1 = (iy0 >= 0 && iy0 <= Hv-2) ? 1 : 0;
        int dx1 = (ix0 >= 0 && ix0 <= Wv-2) ? 1 : 0;
        sBase[idx] = iy0c | (ix0c<<8) | (dy1<<16) | (dx1<<17);
    }
    __syncthreads();

    const float* srcB = src + (size_t)b*Cv*HWv;
    const int pl = tid & 127, jh = tid >> 7;

    // ldmatrix addresses (chunk-invariant)
    const int rowA = wid*16 + (lane & 7) + ((lane & 8) ? 8 : 0);
    const int kwA  = (lane & 16) ? 4 : 0;
    const uint32_t adrAH = sbu + DS_AH + rowA*(AST*4) + kwA*4;
    const uint32_t adrAL = adrAH + (DS_AL - DS_AH);
    const int rowBl = (lane & 7) + ((lane & 16) ? 8 : 0);
    const int kwB   = (lane & 8) ? 4 : 0;
    uint32_t adrBH[4], adrBL[4];
    #pragma unroll
    for (int np = 0; np < 4; np++) {
        adrBH[np] = sbu + DS_BH + ((np*16 + rowBl)*AST)*4 + kwB*4;
        adrBL[np] = adrBH[np] + (DS_BL - DS_BH);
    }

    float acc[8][4];
    #pragma unroll
    for (int nt = 0; nt < 8; nt++)
        #pragma unroll
        for (int e = 0; e < 4; e++) acc[nt][e] = 0.f;

    for (int cc = 0; cc < NCH; cc++) {
        if (cc) __syncthreads();

        // stage B chunk hi/lo: 64 o x 32 words
        #pragma unroll
        for (int it = 0; it < 8; it++) {
            int idx = it*256 + tid;
            int o = idx >> 5, jw = idx & 31;
            int gofs = o*CKK + cc*CKC + 2*jw;
            *(uint32_t*)(smem + DS_BH + (o*AST + jw)*4) = *(const uint32_t*)(wh + gofs);
            *(uint32_t*)(smem + DS_BL + (o*AST + jw)*4) = *(const uint32_t*)(wl + gofs);
        }

        // sample A chunk: 16 words/thread as 4 STS.128 quads
        #pragma unroll
        for (int q = 0; q < 4; q++) {
            int jq = jh*4 + q;
            uint32_t hq[4], lq[4];
            #pragma unroll
            for (int wi = 0; wi < 4; wi++) {
                float s[2];
                #pragma unroll
                for (int e = 0; e < 2; e++) {
                    int ck = cc*CKC + 8*jq + 2*wi + e;
                    int c = ck/9, k = ck - 9*c;
                    int gi = k*MT + pl;
                    float4 cw = sWgt[gi];
                    int ev = sBase[gi];
                    int iy0 = ev & 255, ix0 = (ev>>8) & 255;
                    int iy1 = iy0 + ((ev>>16)&1), ix1 = ix0 + ((ev>>17)&1);
                    const float* xc = srcB + (size_t)c*HWv;
                    s[e] = cw.x*__ldg(xc+iy0*Wv+ix0) + cw.y*__ldg(xc+iy0*Wv+ix1)
                         + cw.z*__ldg(xc+iy1*Wv+ix0) + cw.w*__ldg(xc+iy1*Wv+ix1);
                }
                uint32_t p0 = split_pack(s[0]), p1 = split_pack(s[1]);
                hq[wi] = __byte_perm(p0, p1, 0x5410);
                lq[wi] = __byte_perm(p0, p1, 0x7632);
            }
            *(uint4*)(smem + DS_AH + pl*(AST*4) + jq*16) = make_uint4(hq[0],hq[1],hq[2],hq[3]);
            *(uint4*)(smem + DS_AL + pl*(AST*4) + jq*16) = make_uint4(lq[0],lq[1],lq[2],lq[3]);
        }
        __syncthreads();

        // MMA: 4 k-steps x 8 n-tiles x 3 passes, ldmatrix fragments
        #pragma unroll
        for (int ks = 0; ks < 4; ks++) {
            uint32_t aH0,aH1,aH2,aH3, aL0,aL1,aL2,aL3;
            ldm_x4(aH0,aH1,aH2,aH3, adrAH + ks*32);
            ldm_x4(aL0,aL1,aL2,aL3, adrAL + ks*32);
            #pragma unroll
            for (int np = 0; np < 4; np++) {
                uint32_t bh0,bh1,bh2,bh3, bl0,bl1,bl2,bl3;
                ldm_x4(bh0,bh1,bh2,bh3, adrBH[np] + ks*32);
                ldm_x4(bl0,bl1,bl2,bl3, adrBL[np] + ks*32);
                mma_bf16(acc[2*np],   aH0,aH1,aH2,aH3, bh0,bh1);
                mma_bf16(acc[2*np],   aH0,aH1,aH2,aH3, bl0,bl1);
                mma_bf16(acc[2*np],   aL0,aL1,aL2,aL3, bh0,bh1);
                mma_bf16(acc[2*np+1], aH0,aH1,aH2,aH3, bh2,bh3);
                mma_bf16(acc[2*np+1], aH0,aH1,aH2,aH3, bl2,bl3);
                mma_bf16(acc[2*np+1], aL0,aL1,aL2,aL3, bh2,bh3);
            }
        }
    }

    // epilogue: BN (+residual) + exact GELU (+ mid hi/lo split for pass 1)
    const int px0 = P0 + wid*16 + g;
    const size_t bofs = (size_t)b*Cv*HWv;
    #pragma unroll
    for (int nt = 0; nt < 8; nt++) {
        #pragma unroll
        for (int e = 0; e < 4; e++) {
            int o  = nt*8 + 2*tq + (e & 1);
            int px = px0 + (e >> 1)*8;
            float v = acc[nt][e] * sSc[o] + sSh[o];
            size_t ofs = bofs + (size_t)o*HWv + px;
            if (identity) v += __ldg(identity + ofs);
            v = gelu_exact(v);
            out[ofs] = v;
            if (midhl) midhl[ofs] = split_pack(v);
        }
    }
}

// ---------------------------------------------------------------------------
extern "C" void kernel_launch(void* const* d_in, const int* in_sizes, int n_in,
                              void* d_out, int out_size)
{
    const float* x      = (const float*)d_in[0];
    const float* w_om1  = (const float*)d_in[1];
    const float* b_om1  = (const float*)d_in[2];
    const float* w_dcn1 = (const float*)d_in[3];
    const float* bn1g   = (const float*)d_in[4];
    const float* bn1b   = (const float*)d_in[5];
    const float* bn1m   = (const float*)d_in[6];
    const float* bn1v   = (const float*)d_in[7];
    const float* w_om2  = (const float*)d_in[8];
    const float* b_om2  = (const float*)d_in[9];
    const float* w_dcn2 = (const float*)d_in[10];
    const float* bn2g   = (const float*)d_in[11];
    const float* bn2b   = (const float*)d_in[12];
    const float* bn2m   = (const float*)d_in[13];
    const float* bn2v   = (const float*)d_in[14];
    float* out = (float*)d_out;

    float *om, *mid;
    uint32_t *xhl, *midhl;
    __nv_bfloat16 *wh1, *wl1, *wh2, *wl2, *omh1, *oml1, *omh2, *oml2;
    cudaGetSymbolAddress((void**)&om,    g_om);
    cudaGetSymbolAddress((void**)&mid,   g_mid);
    cudaGetSymbolAddress((void**)&xhl,   g_xhl);
    cudaGetSymbolAddress((void**)&midhl, g_midhl);
    cudaGetSymbolAddress((void**)&wh1,   g_wh1);
    cudaGetSymbolAddress((void**)&wl1,   g_wl1);
    cudaGetSymbolAddress((void**)&wh2,   g_wh2);
    cudaGetSymbolAddress((void**)&wl2,   g_wl2);
    cudaGetSymbolAddress((void**)&omh1,  g_omh1);
    cudaGetSymbolAddress((void**)&oml1,  g_oml1);
    cudaGetSymbolAddress((void**)&omh2,  g_omh2);
    cudaGetSymbolAddress((void**)&oml2,  g_oml2);

    cudaFuncSetAttribute(offc_mma_kernel, cudaFuncAttributeMaxDynamicSharedMemorySize, OS_TOT);
    cudaFuncSetAttribute(dcn_mma_kernel,  cudaFuncAttributeMaxDynamicSharedMemorySize, DS_TOT);

    prep_kernel<<<(Bv*Cv*HWv + 255)/256, 256>>>(x, w_dcn1, w_dcn2, w_om1, w_om2);

    dim3 grid(HWv/MT, Bv);   // 200 x 4

    offc_mma_kernel<<<grid, 256, OS_TOT>>>(xhl, omh1, oml1, b_om1, om);
    dcn_mma_kernel<<<grid, 256, DS_TOT>>>(x, wh1, wl1,
        bn1g, bn1b, bn1m, bn1v, nullptr, mid, midhl);

    offc_mma_kernel<<<grid, 256, OS_TOT>>>(midhl, omh2, oml2, b_om2, om);
    dcn_mma_kernel<<<grid, 256, DS_TOT>>>(mid, wh2, wl2,
        bn2g, bn2b, bn2m, bn2v, x, out, nullptr);
}